// round 17
// baseline (speedup 1.0000x reference)
#include <cuda_runtime.h>
#include <cuda_fp16.h>
#include <math.h>
#include <stdint.h>

// Problem constants
#define LL 1024
#define BB 4
#define DD 1024
#define HH 16
#define HDIM 64
#define DFF_ 4096
#define NROWS 4096        // L*B
#define QKVW 3072         // 3*D

// ---------------- scratch (device globals; no allocation allowed) ------------
__device__ __half g_h_h[(size_t)NROWS * DD];
__device__ __half g_qkv_h[(size_t)NROWS * QKVW];
__device__ __half g_attn_h[(size_t)NROWS * DD];
__device__ float  g_x1[(size_t)NROWS * DD];
__device__ __half g_h2_h[(size_t)NROWS * DD];
__device__ __half g_ff_h[(size_t)NROWS * DFF_];
__device__ __half g_w1[(size_t)QKVW * DD];
__device__ __half g_w2[(size_t)DD * DD];
__device__ __half g_w3[(size_t)DFF_ * DD];
__device__ __half g_w4[(size_t)DD * DFF_];

// ---------------- helpers ----------------------------------------------------
__device__ __forceinline__ uint32_t smem_u32(const void* p) {
    uint32_t a;
    asm("{ .reg .u64 t; cvta.to.shared.u64 t, %1; cvt.u32.u64 %0, t; }" : "=r"(a) : "l"(p));
    return a;
}
#define SWZ128(o) ((o) ^ (((o) >> 3) & 0x70))

#define CP16(s, g) asm volatile("cp.async.cg.shared.global [%0], [%1], 16;\n" :: "r"(s), "l"(g) : "memory")
#define CP_COMMIT() asm volatile("cp.async.commit_group;\n" ::: "memory")
#define CP_WAIT1()  asm volatile("cp.async.wait_group 1;\n" ::: "memory")
#define CP_WAIT0()  asm volatile("cp.async.wait_group 0;\n" ::: "memory")

#define LDSM4(r, addr) \
    asm volatile("ldmatrix.sync.aligned.m8n8.x4.shared.b16 {%0,%1,%2,%3}, [%4];" \
        : "=r"((r)[0]), "=r"((r)[1]), "=r"((r)[2]), "=r"((r)[3]) : "r"(addr))
#define LDSM4T(r, addr) \
    asm volatile("ldmatrix.sync.aligned.m8n8.x4.trans.shared.b16 {%0,%1,%2,%3}, [%4];" \
        : "=r"((r)[0]), "=r"((r)[1]), "=r"((r)[2]), "=r"((r)[3]) : "r"(addr))

#define MMAH(d, a, b0, b1) \
    asm volatile("mma.sync.aligned.m16n8k16.row.col.f32.f16.f16.f32 " \
        "{%0,%1,%2,%3}, {%4,%5,%6,%7}, {%8,%9}, {%0,%1,%2,%3};" \
        : "+f"((d)[0]), "+f"((d)[1]), "+f"((d)[2]), "+f"((d)[3]) \
        : "r"((a)[0]), "r"((a)[1]), "r"((a)[2]), "r"((a)[3]), "r"(b0), "r"(b1))

__device__ __forceinline__ uint32_t pack_h2(float a, float b) {
    __half2 h = __floats2half2_rn(a, b);
    return *reinterpret_cast<uint32_t*>(&h);
}

// ---------------- merged weight convert: fp32 -> fp16, all 4 weights ---------
#define W1N (QKVW * DD)
#define W2N (DD * DD)
#define W3N (DFF_ * DD)
#define W4N (DD * DFF_)
__global__ void conv_all_kernel(const float* __restrict__ s1, const float* __restrict__ s2,
                                const float* __restrict__ s3, const float* __restrict__ s4,
                                __half* __restrict__ d1, __half* __restrict__ d2,
                                __half* __restrict__ d3, __half* __restrict__ d4) {
    int i = (blockIdx.x * 256 + threadIdx.x) * 4;
    const float* src; __half* dst;
    if (i < W1N)                   { src = s1; dst = d1; }
    else if (i < W1N + W2N)        { i -= W1N; src = s2; dst = d2; }
    else if (i < W1N + W2N + W3N)  { i -= W1N + W2N; src = s3; dst = d3; }
    else                           { i -= W1N + W2N + W3N; src = s4; dst = d4; }
    float4 v = *(const float4*)(src + i);
    uint32_t p0 = pack_h2(v.x, v.y), p1 = pack_h2(v.z, v.w);
    *(uint32_t*)&dst[i]     = p0;
    *(uint32_t*)&dst[i + 2] = p1;
}

// ---------------- LayerNorm -> fp16 ------------------------------------------
__global__ void ln_h_kernel(const float* __restrict__ X, const float* __restrict__ w,
                            const float* __restrict__ b, __half* __restrict__ Y) {
    int row = blockIdx.x;
    int tid = threadIdx.x;
    const float* xr = X + (size_t)row * DD;
    float v0 = xr[tid], v1 = xr[tid + 256], v2 = xr[tid + 512], v3 = xr[tid + 768];
    float s = v0 + v1 + v2 + v3;
    float s2 = v0 * v0 + v1 * v1 + v2 * v2 + v3 * v3;
    #pragma unroll
    for (int off = 16; off; off >>= 1) {
        s  += __shfl_xor_sync(0xffffffffu, s, off);
        s2 += __shfl_xor_sync(0xffffffffu, s2, off);
    }
    __shared__ float sh[16];
    __shared__ float smean, sinv;
    int wid = tid >> 5, lid = tid & 31;
    if (lid == 0) { sh[wid] = s; sh[wid + 8] = s2; }
    __syncthreads();
    if (wid == 0) {
        float a  = (lid < 8) ? sh[lid] : 0.f;
        float a2 = (lid < 8) ? sh[lid + 8] : 0.f;
        #pragma unroll
        for (int off = 4; off; off >>= 1) {
            a  += __shfl_xor_sync(0xffffffffu, a, off, 8);
            a2 += __shfl_xor_sync(0xffffffffu, a2, off, 8);
        }
        if (lid == 0) {
            float mean = a * (1.f / DD);
            float var = a2 * (1.f / DD) - mean * mean;
            smean = mean;
            sinv = rsqrtf(var + 1e-5f);
        }
    }
    __syncthreads();
    float mean = smean, inv = sinv;
    size_t base = (size_t)row * DD;
    #pragma unroll
    for (int q = 0; q < 4; q++) {
        int c = tid + q * 256;
        float v = (q == 0 ? v0 : q == 1 ? v1 : q == 2 ? v2 : v3);
        Y[base + c] = __float2half((v - mean) * inv * w[c] + b[c]);
    }
}

// ---------------- mma.sync fp16 GEMM, CTA 128x128, K-chunk 64, 2 CTA/SM ------
// Raster-swizzled: co-resident CTAs share B columns (8-deep m groups).
// EPI: 1 = gelu(+bias) -> fp16 ; 2 = +bias+Res -> fp32 ; 3 = +bias -> fp16
#define GB_STRIDE 32768
__global__ void __launch_bounds__(256, 2)
gemm_mma(const __half* __restrict__ A, const __half* __restrict__ B,
         const float* __restrict__ bias, const float* __restrict__ Res,
         float* __restrict__ OutF, __half* __restrict__ OutH,
         int M, int N, int K, int EPI) {
    extern __shared__ __align__(1024) char smem[];
    uint32_t sb = smem_u32(smem);
    int tid = threadIdx.x;
    int w = tid >> 5, lane = tid & 31;
    int wm = w & 3, wn = w >> 2;            // 4 m-strips(32) x 2 n-strips(64)

    // CTA raster swizzle: 8 consecutive m-blocks per n-column group
    int nbx = gridDim.x;
    int bid = blockIdx.y * nbx + blockIdx.x;
    int width = nbx * 8;
    int grp = bid / width;
    int rem = bid - grp * width;
    int m0 = (grp * 8 + (rem & 7)) * 128;
    int n0 = (rem >> 3) * 128;
    const int nc = K >> 6;

    float acc[2][8][4];
    #pragma unroll
    for (int i = 0; i < 2; i++)
        #pragma unroll
        for (int j = 0; j < 8; j++)
            #pragma unroll
            for (int r = 0; r < 4; r++) acc[i][j][r] = 0.f;

    int rowA = (lane & 7) + (((lane >> 3) & 1) << 3);
    int kbA  = ((lane >> 4) & 1) << 4;
    int rowB = (lane & 7) + (((lane >> 4) & 1) << 3);
    int kbB  = ((lane >> 3) & 1) << 4;

    #define GLOAD(buf, k0)                                                       \
    {                                                                            \
        uint32_t bA = sb + (buf) * GB_STRIDE;                                    \
        _Pragma("unroll")                                                        \
        for (int i = 0; i < 4; i++) {                                            \
            int id = tid + (i << 8);                                             \
            int row = id >> 3, c = id & 7;                                       \
            uint32_t so = SWZ128((uint32_t)(row * 128 + c * 16));                \
            CP16(bA + so,         A + (size_t)(m0 + row) * K + (k0) + c * 8);    \
            CP16(bA + 16384 + so, B + (size_t)(n0 + row) * K + (k0) + c * 8);    \
        }                                                                        \
    }

    GLOAD(0, 0);
    CP_COMMIT();

    for (int kc = 0; kc < nc; kc++) {
        int b = kc & 1;
        if (kc + 1 < nc) {
            if (kc >= 1) __syncthreads();
            GLOAD(b ^ 1, (kc + 1) << 6);
            CP_COMMIT();
            CP_WAIT1();
        } else {
            CP_WAIT0();
        }
        __syncthreads();

        uint32_t tb = sb + b * GB_STRIDE;
        #pragma unroll
        for (int ks = 0; ks < 4; ks++) {
            int kb = ks * 32;
            uint32_t ah[2][4], bh[4][4];
            #pragma unroll
            for (int mt = 0; mt < 2; mt++) {
                uint32_t off = SWZ128((uint32_t)((wm * 32 + mt * 16 + rowA) * 128 + kb + kbA));
                LDSM4(ah[mt], tb + off);
            }
            #pragma unroll
            for (int p = 0; p < 4; p++) {
                uint32_t off = SWZ128((uint32_t)((wn * 64 + p * 16 + rowB) * 128 + kb + kbB));
                LDSM4(bh[p], tb + 16384 + off);
            }
            #pragma unroll
            for (int mt = 0; mt < 2; mt++)
                #pragma unroll
                for (int nt = 0; nt < 8; nt++) {
                    int p = nt >> 1, h = (nt & 1) * 2;
                    MMAH(acc[mt][nt], ah[mt], bh[p][h], bh[p][h + 1]);
                }
        }
    }

    int gr = lane >> 2, tg = lane & 3;
    #pragma unroll
    for (int mt = 0; mt < 2; mt++) {
        #pragma unroll
        for (int nt = 0; nt < 8; nt++) {
            int r0 = m0 + wm * 32 + mt * 16 + gr;
            int c  = n0 + wn * 64 + nt * 8 + tg * 2;
            float b0 = __ldg(&bias[c]), b1 = __ldg(&bias[c + 1]);
            float v00 = acc[mt][nt][0] + b0, v01 = acc[mt][nt][1] + b1;
            float v10 = acc[mt][nt][2] + b0, v11 = acc[mt][nt][3] + b1;
            size_t o0 = (size_t)r0 * N + c;
            size_t o1 = (size_t)(r0 + 8) * N + c;
            if (EPI == 1 || EPI == 3) {
                if (EPI == 1) {
                    v00 = 0.5f * v00 * (1.f + erff(v00 * 0.70710678118654752f));
                    v01 = 0.5f * v01 * (1.f + erff(v01 * 0.70710678118654752f));
                    v10 = 0.5f * v10 * (1.f + erff(v10 * 0.70710678118654752f));
                    v11 = 0.5f * v11 * (1.f + erff(v11 * 0.70710678118654752f));
                }
                *(uint32_t*)&OutH[o0] = pack_h2(v00, v01);
                *(uint32_t*)&OutH[o1] = pack_h2(v10, v11);
            } else {
                if (EPI == 2) {
                    float2 r0v = *(const float2*)&Res[o0];
                    float2 r1v = *(const float2*)&Res[o1];
                    v00 += r0v.x; v01 += r0v.y; v10 += r1v.x; v11 += r1v.y;
                }
                *(float2*)&OutF[o0] = make_float2(v00, v01);
                *(float2*)&OutF[o1] = make_float2(v10, v11);
            }
        }
    }
    #undef GLOAD
}

// ---------------- Flash attention, fp16 mma.sync, 2 CTAs/SM ------------------
// CTA: 128 q-rows; 8 warps x 16 rows; key tiles of 128; KV double-buffered,
// edge single buffer prefetched during PV phase (R10 overlap scheme).
// smem: Q 16K | KV 2x16K | edge 34K = 84K -> 2 CTAs/SM.
#define KV_OFF   16384
#define KV_SZ    16384
#define EDGE_OFF 49152
#define EDGE_PITCH 528
#define EDGE_SZ  (128 * EDGE_PITCH / 2)   // placeholder, real size below
__global__ void __launch_bounds__(256, 2)
attn_mma(const __half* __restrict__ qkv, const float* __restrict__ edge,
         float* __restrict__ edge_out, __half* __restrict__ attn_o) {
    extern __shared__ __align__(1024) char smem[];
    uint32_t sb = smem_u32(smem);
    int bh = blockIdx.y;
    int q0 = blockIdx.x * 128;
    int b = bh >> 4, hh = bh & 15;
    int tid = threadIdx.x, lane = tid & 31, wr = tid >> 5;
    int g = lane >> 2, tg = lane & 3;

    size_t ebase0 = ((size_t)bh << 20) + (size_t)q0 * LL;

    // prologue: Q + KV(0)->buf0 + edge(0), one group
    #pragma unroll
    for (int i = 0; i < 4; i++) {
        int id = tid + i * 256;
        int r = id >> 3, c = id & 7;
        uint32_t so = SWZ128((uint32_t)(r * 128 + c * 16));
        CP16(sb + so, qkv + ((size_t)(q0 + r) * BB + b) * QKVW + hh * HDIM + c * 8);
    }
    #pragma unroll
    for (int i = 0; i < 4; i++) {
        int id = tid + i * 256;
        int a = id >> 9;                       // 0 = K, 1 = V (512 chunks each)
        int r = (id >> 3) & 63, c = id & 7;    // wait: 128 keys x 8 chunks = 1024
        (void)a; (void)r; (void)c;
    }
    // K/V tile: 128 keys x 64 d fp16 = 16 KB each? No: 128 x 128B = 16 KB each.
    // KV buffer holds K (8 KB? no). Recompute: 128 keys x 64 d x 2B = 16 KB per
    // tensor -> KV_SZ must be 32 KB. Fix: K at +0, V at +16384, KV_SZ 32768.
    #pragma unroll
    for (int i = 0; i < 8; i++) {
        int id = tid + i * 256;
        int a = id >> 10;                      // 0 = K, 1 = V
        int r = (id >> 3) & 127, c = id & 7;
        uint32_t so = SWZ128((uint32_t)(r * 128 + c * 16));
        size_t off = ((size_t)r * BB + b) * QKVW + hh * HDIM + c * 8 + (a ? 2 * DD : DD);
        CP16(sb + KV_OFF + a * 16384 + so, qkv + off);
    }
    #pragma unroll
    for (int i = 0; i < 16; i++) {
        int id = tid + i * 256;
        int r = id >> 5, c = id & 31;
        CP16(sb + EDGE_OFF + 32768 + r * EDGE_PITCH + c * 16,
             edge + ebase0 + (size_t)r * LL + c * 4);
    }
    CP_COMMIT(); CP_WAIT0(); __syncthreads();

    int rowA = (lane & 7) + (((lane >> 3) & 1) << 3);
    int kbA  = ((lane >> 4) & 1) << 4;
    uint32_t qa[4][4];
    #pragma unroll
    for (int ks = 0; ks < 4; ks++) {
        uint32_t off = SWZ128((uint32_t)((wr * 16 + rowA) * 128 + ks * 32 + kbA));
        LDSM4(qa[ks], sb + off);
    }

    float m_run[2] = {-1e30f, -1e30f}, l_run[2] = {0.f, 0.f};
    float Oacc[8][4];
    #pragma unroll
    for (int i = 0; i < 8; i++)
        #pragma unroll
        for (int r = 0; r < 4; r++) Oacc[i][r] = 0.f;

    int rowB = (lane & 7) + (((lane >> 4) & 1) << 3);
    int kbB  = ((lane >> 3) & 1) << 4;
    int rowV = lane & 15, dcV = ((lane >> 4) & 1) * 8;
    int erow = (wr * 16 + g) * EDGE_PITCH + tg * 8;
    uint32_t eb = sb + EDGE_OFF + 32768;     // single edge buffer

    for (int kt = 0; kt < 8; kt++) {
        int bf = kt & 1;
        __syncthreads();                      // PV(kt-1) done: KV buf bf^1 free
        if (kt + 1 < 8) {                     // prefetch KV(kt+1)
            int k0n = (kt + 1) * 128;
            uint32_t kvb = sb + KV_OFF + (bf ^ 1) * 32768;
            #pragma unroll
            for (int i = 0; i < 8; i++) {
                int id = tid + i * 256;
                int a = id >> 10;
                int r = (id >> 3) & 127, c = id & 7;
                uint32_t so = SWZ128((uint32_t)(r * 128 + c * 16));
                size_t off = ((size_t)(k0n + r) * BB + b) * QKVW + hh * HDIM + c * 8
                           + (a ? 2 * DD : DD);
                CP16(kvb + a * 16384 + so, qkv + off);
            }
            CP_COMMIT();
            CP_WAIT1();                       // KV(kt) + edge(kt) resident
        } else {
            CP_WAIT0();
        }
        __syncthreads();

        uint32_t tb = sb + KV_OFF + bf * 32768;
        int k0 = kt * 128;

        // S = Q K^T
        float S[16][4];
        #pragma unroll
        for (int i = 0; i < 16; i++)
            #pragma unroll
            for (int r = 0; r < 4; r++) S[i][r] = 0.f;
        #pragma unroll
        for (int ks = 0; ks < 4; ks++) {
            #pragma unroll
            for (int j = 0; j < 8; j++) {
                uint32_t kh[4];
                uint32_t off = SWZ128((uint32_t)((j * 16 + rowB) * 128 + ks * 32 + kbB));
                LDSM4(kh, tb + off);
                MMAH(S[2 * j],     qa[ks], kh[0], kh[1]);
                MMAH(S[2 * j + 1], qa[ks], kh[2], kh[3]);
            }
        }

        // t = S/8 + edge (smem); stream to edge_out
        size_t ebaseg = ((size_t)bh << 20) + (size_t)(q0 + wr * 16 + g) * LL + k0 + tg * 2;
        #pragma unroll
        for (int nt = 0; nt < 16; nt++) {
            float2 ea = *(const float2*)(smem + (eb - sb) + erow + nt * 32);
            float2 ebv = *(const float2*)(smem + (eb - sb) + erow + nt * 32 + 8 * EDGE_PITCH);
            S[nt][0] = fmaf(S[nt][0], 0.125f, ea.x);
            S[nt][1] = fmaf(S[nt][1], 0.125f, ea.y);
            S[nt][2] = fmaf(S[nt][2], 0.125f, ebv.x);
            S[nt][3] = fmaf(S[nt][3], 0.125f, ebv.y);
            size_t e0 = ebaseg + nt * 8;
            *(float2*)&edge_out[e0]          = make_float2(S[nt][0], S[nt][1]);
            *(float2*)&edge_out[e0 + 8 * LL] = make_float2(S[nt][2], S[nt][3]);
        }

        // online softmax
        float mx0 = -1e30f, mx1 = -1e30f;
        #pragma unroll
        for (int nt = 0; nt < 16; nt++) {
            mx0 = fmaxf(mx0, fmaxf(S[nt][0], S[nt][1]));
            mx1 = fmaxf(mx1, fmaxf(S[nt][2], S[nt][3]));
        }
        mx0 = fmaxf(mx0, __shfl_xor_sync(0xffffffffu, mx0, 1));
        mx0 = fmaxf(mx0, __shfl_xor_sync(0xffffffffu, mx0, 2));
        mx1 = fmaxf(mx1, __shfl_xor_sync(0xffffffffu, mx1, 1));
        mx1 = fmaxf(mx1, __shfl_xor_sync(0xffffffffu, mx1, 2));
        float mn0 = fmaxf(m_run[0], mx0), mn1 = fmaxf(m_run[1], mx1);
        float corr0 = __expf(m_run[0] - mn0), corr1 = __expf(m_run[1] - mn1);
        float s0 = 0.f, s1 = 0.f;
        #pragma unroll
        for (int nt = 0; nt < 16; nt++) {
            S[nt][0] = __expf(S[nt][0] - mn0); s0 += S[nt][0];
            S[nt][1] = __expf(S[nt][1] - mn0); s0 += S[nt][1];
            S[nt][2] = __expf(S[nt][2] - mn1); s1 += S[nt][2];
            S[nt][3] = __expf(S[nt][3] - mn1); s1 += S[nt][3];
        }
        s0 += __shfl_xor_sync(0xffffffffu, s0, 1);
        s0 += __shfl_xor_sync(0xffffffffu, s0, 2);
        s1 += __shfl_xor_sync(0xffffffffu, s1, 1);
        s1 += __shfl_xor_sync(0xffffffffu, s1, 2);
        l_run[0] = l_run[0] * corr0 + s0; m_run[0] = mn0;
        l_run[1] = l_run[1] * corr1 + s1; m_run[1] = mn1;
        #pragma unroll
        for (int nt = 0; nt < 8; nt++) {
            Oacc[nt][0] *= corr0; Oacc[nt][1] *= corr0;
            Oacc[nt][2] *= corr1; Oacc[nt][3] *= corr1;
        }

        // edge smem consumed; prefetch edge(kt+1) overlapping PV
        __syncthreads();
        if (kt + 1 < 8) {
            size_t ebn = ebase0 + (size_t)(kt + 1) * 128;
            #pragma unroll
            for (int i = 0; i < 16; i++) {
                int id = tid + i * 256;
                int r = id >> 5, c = id & 31;
                CP16(eb + r * EDGE_PITCH + c * 16, edge + ebn + (size_t)r * LL + c * 4);
            }
            CP_COMMIT();
        }

        // O += P V
        #pragma unroll
        for (int j = 0; j < 8; j++) {
            uint32_t ah[4];
            ah[0] = pack_h2(S[2 * j][0],     S[2 * j][1]);
            ah[1] = pack_h2(S[2 * j][2],     S[2 * j][3]);
            ah[2] = pack_h2(S[2 * j + 1][0], S[2 * j + 1][1]);
            ah[3] = pack_h2(S[2 * j + 1][2], S[2 * j + 1][3]);
            uint32_t vh[4][4];
            #pragma unroll
            for (int dg = 0; dg < 4; dg++) {
                uint32_t off = SWZ128((uint32_t)((j * 16 + rowV) * 128 + (dg * 16 + dcV) * 2));
                LDSM4T(vh[dg], tb + 16384 + off);
            }
            #pragma unroll
            for (int dg = 0; dg < 4; dg++) {
                MMAH(Oacc[2 * dg],     ah, vh[dg][0], vh[dg][1]);
                MMAH(Oacc[2 * dg + 1], ah, vh[dg][2], vh[dg][3]);
            }
        }
    }

    // finalize
    float inv0 = 1.f / l_run[0], inv1 = 1.f / l_run[1];
    int r0 = q0 + wr * 16 + g;
    #pragma unroll
    for (int nt = 0; nt < 8; nt++) {
        int d = hh * HDIM + nt * 8 + tg * 2;
        size_t o0 = ((size_t)r0 * BB + b) * DD + d;
        size_t o1 = ((size_t)(r0 + 8) * BB + b) * DD + d;
        *(uint32_t*)&attn_o[o0] = pack_h2(Oacc[nt][0] * inv0, Oacc[nt][1] * inv0);
        *(uint32_t*)&attn_o[o1] = pack_h2(Oacc[nt][2] * inv1, Oacc[nt][3] * inv1);
    }
}

// ---------------- host orchestration ----------------------------------------
extern "C" void kernel_launch(void* const* d_in, const int* in_sizes, int n_in,
                              void* d_out, int out_size) {
    const float* x         = (const float*)d_in[0];
    const float* edge      = (const float*)d_in[1];
    const float* in_proj_w = (const float*)d_in[2];
    const float* in_proj_b = (const float*)d_in[3];
    const float* out_proj_w= (const float*)d_in[4];
    const float* out_proj_b= (const float*)d_in[5];
    const float* lin1_w    = (const float*)d_in[6];
    const float* lin1_b    = (const float*)d_in[7];
    const float* lin2_w    = (const float*)d_in[8];
    const float* lin2_b    = (const float*)d_in[9];
    const float* norm1_w   = (const float*)d_in[10];
    const float* norm1_b   = (const float*)d_in[11];
    const float* norm2_w   = (const float*)d_in[12];
    const float* norm2_b   = (const float*)d_in[13];

    float* out_x    = (float*)d_out;
    float* edge_out = (float*)d_out + (size_t)NROWS * DD;

    __half *h_h, *qkv_h, *attn_h, *h2_h, *ff_h, *w1, *w2, *w3, *w4;
    float *x1;
    cudaGetSymbolAddress((void**)&h_h, g_h_h);
    cudaGetSymbolAddress((void**)&qkv_h, g_qkv_h);
    cudaGetSymbolAddress((void**)&attn_h, g_attn_h);
    cudaGetSymbolAddress((void**)&x1, g_x1);
    cudaGetSymbolAddress((void**)&h2_h, g_h2_h);
    cudaGetSymbolAddress((void**)&ff_h, g_ff_h);
    cudaGetSymbolAddress((void**)&w1, g_w1);
    cudaGetSymbolAddress((void**)&w2, g_w2);
    cudaGetSymbolAddress((void**)&w3, g_w3);
    cudaGetSymbolAddress((void**)&w4, g_w4);

    int gemm_smem = 2 * GB_STRIDE;                    // 65536
    cudaFuncSetAttribute(gemm_mma, cudaFuncAttributeMaxDynamicSharedMemorySize, gemm_smem);
    // smem: Q 16K @0 | KV 2x32K @16384 | edge 67584 @81920  -> 16K+64K+33.75K... 
    // actual layout: KV_OFF=16384, KV bufs at 16384, 49152; EDGE at 81920.
    // Recomputed inside kernel as: KV buf stride 32768, edge at EDGE_OFF+32768.
    int attn_smem = EDGE_OFF + 32768 + 128 * EDGE_PITCH;   // 49152+32768+67584 = 149504? no:
    attn_smem = 16384 + 2 * 32768 + 128 * EDGE_PITCH;      // 16K + 64K + 66K = 149504
    cudaFuncSetAttribute(attn_mma, cudaFuncAttributeMaxDynamicSharedMemorySize, attn_smem);

    // 0. convert all weights to fp16 (one launch)
    conv_all_kernel<<<(W1N + W2N + W3N + W4N) / 1024, 256>>>(
        in_proj_w, out_proj_w, lin1_w, lin2_w, w1, w2, w3, w4);

    // 1. h = LN1(x) -> fp16
    ln_h_kernel<<<NROWS, 256>>>(x, norm1_w, norm1_b, h_h);

    // 2. qkv = h @ in_proj_w^T + b -> fp16 (EPI 3)
    gemm_mma<<<dim3(QKVW / 128, NROWS / 128), 256, gemm_smem>>>(
        h_h, w1, in_proj_b, nullptr, nullptr, qkv_h, NROWS, QKVW, DD, 3);

    // 3. attention: edge_out + attn fp16
    attn_mma<<<dim3(8, 64), 256, attn_smem>>>(qkv_h, edge, edge_out, attn_h);

    // 4. x1 = x + attn @ out_proj_w^T + b (fp32)
    gemm_mma<<<dim3(DD / 128, NROWS / 128), 256, gemm_smem>>>(
        attn_h, w2, out_proj_b, x, x1, nullptr, NROWS, DD, DD, 2);

    // 5. h2 = LN2(x1) -> fp16
    ln_h_kernel<<<NROWS, 256>>>(x1, norm2_w, norm2_b, h2_h);

    // 6. ff = gelu(h2 @ lin1_w^T + b) -> fp16
    gemm_mma<<<dim3(DFF_ / 128, NROWS / 128), 256, gemm_smem>>>(
        h2_h, w3, lin1_b, nullptr, nullptr, ff_h, NROWS, DFF_, DD, 1);

    // 7. out_x = x1 + ff @ lin2_w^T + b (fp32)
    gemm_mma<<<dim3(DD / 128, NROWS / 128), 256, gemm_smem>>>(
        ff_h, w4, lin2_b, x1, out_x, nullptr, NROWS, DD, DFF_, 2);
}